// round 11
// baseline (speedup 1.0000x reference)
#include <cuda_runtime.h>
#include <math.h>

#define D_IN 768
#define NQ_MAX 512
#define NC_MAX 65536
#define EPSF 1e-7f

typedef unsigned long long ull;

// Scratch: corpus features transposed [feature k][corpus idx], plus per-row extras.
__device__ float g_cT[64 * NC_MAX];     // k-major corpus features (e:0..31, h:32..47, s:48..63)
__device__ float g_yn[NC_MAX];          // ||c_h||^2 = tanh(n)^2
__device__ float g_qT[64 * NQ_MAX];     // k-major query features
__device__ float g_xn[NQ_MAX];          // ||q_h||^2
__device__ float g_w[3 * NQ_MAX];       // softplus weights per query

// packed f32x2 FMA: d = a*b + d (lanewise on 2 packed floats)
__device__ __forceinline__ void ffma2(ull& d, ull a, ull b) {
    asm("fma.rn.f32x2 %0, %1, %2, %0;" : "+l"(d) : "l"(a), "l"(b));
}
__device__ __forceinline__ float fold2(ull v) {
    return __uint_as_float((unsigned)v) + __uint_as_float((unsigned)(v >> 32));
}
// fast sqrt for strictly-positive x (1 MUFU + 1 mul)
__device__ __forceinline__ float fsqrt_pos(float x) { return x * rsqrtf(x); }
// acos via A&S 4.4.46 (7-term), |abs err| ~2e-8. Input must be in [-1,1].
__device__ __forceinline__ float facos(float x) {
    float t = fabsf(x);
    float u = 1.0f - t;                  // >= EPSF after caller's clamp
    float s = u * rsqrtf(u);             // sqrt(1-t)
    float p = fmaf(t, -0.0012624911f, 0.0066700901f);
    p = fmaf(t, p, -0.0170881256f);
    p = fmaf(t, p,  0.0308918810f);
    p = fmaf(t, p, -0.0501743046f);
    p = fmaf(t, p,  0.0889789874f);
    p = fmaf(t, p, -0.2145988016f);
    p = fmaf(t, p,  1.5707963050f);
    float r = s * p;
    return (x < 0.f) ? (3.14159265358979f - r) : r;
}

// ---------------------------------------------------------------------------
// Kernel A: corpus projection. Block = 64 corpus rows, 128 threads.
// thread (kp = tid&31, rg = tid>>5) computes features kp AND kp+32 for rows
// rg*16 .. rg*16+15. Packed-k f32x2; x loads broadcast, amortized over 2 feats.
// ---------------------------------------------------------------------------
#define XSTRIDE 34   // float2 units per row (32 kk + 2 pad); conflict-free

__global__ __launch_bounds__(128, 3) void corpus_proj_kernel(
    const float* __restrict__ xc,
    const float* __restrict__ We, const float* __restrict__ be,
    const float* __restrict__ Wh, const float* __restrict__ bh,
    const float* __restrict__ Ws, const float* __restrict__ bs,
    const float* __restrict__ scale_h_p, int NC)
{
    __shared__ __align__(16) float pool[2 * 64 * XSTRIDE * 2];
    __shared__ float sm_yn[64];
    float2* xs2 = (float2*)pool;                    // [row][kk]
    float2* wt2 = (float2*)pool + 64 * XSTRIDE;     // [feat][kk]

    const int tid = threadIdx.x;
    const int kp  = tid & 31;          // feature A = kp (e), feature B = kp+32 (h/s)
    const int rg  = tid >> 5;          // 0..3, 16 rows each
    const int c0  = blockIdx.x * 64;
    const int fB  = kp + 32;

    const float biasA = be[kp];
    const float biasB = (kp < 16) ? bh[kp] : bs[kp - 16];

    ull accA[16], accB[16];
#pragma unroll
    for (int i = 0; i < 16; i++) { accA[i] = 0ull; accB[i] = 0ull; }

    const int j4 = tid & 15;           // float4 column within tile
    const int r0 = tid >> 4;           // 0..7

    for (int k0 = 0; k0 < D_IN; k0 += 64) {
        __syncthreads();
        // x tile: 64 rows x 64 k, float4 LDG -> [row][kk] pairs
#pragma unroll
        for (int it = 0; it < 8; it++) {
            int r = r0 + it * 8;
            float4 v = *(const float4*)&xc[(size_t)(c0 + r) * D_IN + k0 + j4 * 4];
            *(float4*)&xs2[r * XSTRIDE + j4 * 2] = v;
        }
        // weight tile: wt2[kf][kk]
#pragma unroll
        for (int it = 0; it < 8; it++) {
            int kf = r0 + it * 8;
            const float* wr = (kf < 32) ? (We + kf * D_IN)
                            : (kf < 48) ? (Wh + (kf - 32) * D_IN)
                                        : (Ws + (kf - 48) * D_IN);
            float4 v = *(const float4*)&wr[k0 + j4 * 4];
            *(float4*)&wt2[kf * XSTRIDE + j4 * 2] = v;
        }
        __syncthreads();

        const float2* xrow = xs2 + rg * 16 * XSTRIDE;  // uniform per warp -> broadcast
#pragma unroll 4
        for (int kk = 0; kk < 32; kk += 2) {
            ulonglong2 wA = *(const ulonglong2*)&wt2[kp * XSTRIDE + kk];
            ulonglong2 wB = *(const ulonglong2*)&wt2[fB * XSTRIDE + kk];
#pragma unroll
            for (int u = 0; u < 16; u++) {
                ulonglong2 xv = *(const ulonglong2*)&xrow[u * XSTRIDE + kk]; // broadcast
                ffma2(accA[u], xv.x, wA.x);
                ffma2(accA[u], xv.y, wA.y);
                ffma2(accB[u], xv.x, wB.x);
                ffma2(accB[u], xv.y, wB.y);
            }
        }
    }

    // fold packed halves, add bias (+ scale_h for hyperbolic branch)
    const float sh = scale_h_p[0];
    const bool isH = (kp < 16);        // feature B type
    float aA[16], aB[16];
#pragma unroll
    for (int i = 0; i < 16; i++) {
        aA[i] = fold2(accA[i]) + biasA;
        float v = fold2(accB[i]) + biasB;
        if (isH) v *= sh;
        aB[i] = v;
    }

    const unsigned FULL = 0xffffffffu;
    // feature A: e-norm over full warp
#pragma unroll
    for (int i = 0; i < 16; i++) {
        float s = aA[i] * aA[i];
        s += __shfl_xor_sync(FULL, s, 16);
        s += __shfl_xor_sync(FULL, s, 8);
        s += __shfl_xor_sync(FULL, s, 4);
        s += __shfl_xor_sync(FULL, s, 2);
        s += __shfl_xor_sync(FULL, s, 1);
        aA[i] *= rsqrtf(s);
    }
    // feature B: lanes 0..15 = h (expmap0), lanes 16..31 = s; 16-lane groups
#pragma unroll
    for (int i = 0; i < 16; i++) {
        float s = aB[i] * aB[i];
        s += __shfl_xor_sync(FULL, s, 8);
        s += __shfl_xor_sync(FULL, s, 4);
        s += __shfl_xor_sync(FULL, s, 2);
        s += __shfl_xor_sync(FULL, s, 1);
        if (isH) {
            float rs = rsqrtf(fmaxf(s, 1e-30f));   // 1/n
            float n  = s * rs;                      // n = sqrt(s)
            float tn = tanhf(n);
            aB[i] = aB[i] * (tn * rs);
            if (kp == 0) sm_yn[rg * 16 + i] = tn * tn;
        } else {
            aB[i] *= rsqrtf(s);
        }
    }

    // transpose through smem (overlay pool) for coalesced k-major global writes
    __syncthreads();
    float* st = pool;   // needs 64*65 = 4160 floats; pool has 8704
#pragma unroll
    for (int i = 0; i < 16; i++) {
        st[kp * 65 + rg * 16 + i] = aA[i];
        st[fB * 65 + rg * 16 + i] = aB[i];
    }
    __syncthreads();
#pragma unroll
    for (int it = 0; it < 32; it++) {
        int idx = tid + it * 128;
        int kf = idx >> 6, r = idx & 63;
        g_cT[(size_t)kf * NC + c0 + r] = st[kf * 65 + r];
    }
    if (tid < 64) g_yn[c0 + tid] = sm_yn[tid];
}

// ---------------------------------------------------------------------------
// Kernel B: query projection + softplus-MLP weights. One block per query.
// ---------------------------------------------------------------------------
__global__ __launch_bounds__(128) void query_proj_kernel(
    const float* __restrict__ xq,
    const float* __restrict__ We, const float* __restrict__ be,
    const float* __restrict__ Wh, const float* __restrict__ bh,
    const float* __restrict__ Ws, const float* __restrict__ bs,
    const float* __restrict__ scale_h_p,
    const float* __restrict__ W1, const float* __restrict__ b1,
    const float* __restrict__ W2, const float* __restrict__ b2,
    int NQ)
{
    __shared__ float x[D_IN];
    __shared__ float raw[96];
    const int tid = threadIdx.x;
    const int qi  = blockIdx.x;

    for (int j = tid; j < D_IN; j += 128) x[j] = xq[(size_t)qi * D_IN + j];
    __syncthreads();

    if (tid < 96) {
        const float* Wr; float b;
        if (tid < 32)      { Wr = We + tid * D_IN;        b = be[tid]; }
        else if (tid < 48) { Wr = Wh + (tid - 32) * D_IN; b = bh[tid - 32]; }
        else if (tid < 64) { Wr = Ws + (tid - 48) * D_IN; b = bs[tid - 48]; }
        else               { Wr = W1 + (tid - 64) * D_IN; b = b1[tid - 64]; }
        float a0 = 0.f, a1 = 0.f, a2 = 0.f, a3 = 0.f;
#pragma unroll 4
        for (int j = 0; j < D_IN; j += 4) {
            const float4 wv = *(const float4*)&Wr[j];
            a0 = fmaf(x[j + 0], wv.x, a0);
            a1 = fmaf(x[j + 1], wv.y, a1);
            a2 = fmaf(x[j + 2], wv.z, a2);
            a3 = fmaf(x[j + 3], wv.w, a3);
        }
        float acc = (a0 + a1) + (a2 + a3) + b;
        if (tid >= 32 && tid < 48) acc *= scale_h_p[0];
        raw[tid] = acc;
    }
    __syncthreads();

    const unsigned FULL = 0xffffffffu;
    const int warp = tid >> 5, lane = tid & 31;
    if (warp == 0) {
        float v = raw[lane];
        float s = v * v;
        s += __shfl_xor_sync(FULL, s, 16);
        s += __shfl_xor_sync(FULL, s, 8);
        s += __shfl_xor_sync(FULL, s, 4);
        s += __shfl_xor_sync(FULL, s, 2);
        s += __shfl_xor_sync(FULL, s, 1);
        g_qT[(size_t)lane * NQ + qi] = v * rsqrtf(s);
    } else if (warp == 1) {
        float v = (lane < 16) ? raw[32 + lane] : raw[48 + (lane - 16)];
        float s = v * v;
        s += __shfl_xor_sync(FULL, s, 8);
        s += __shfl_xor_sync(FULL, s, 4);
        s += __shfl_xor_sync(FULL, s, 2);
        s += __shfl_xor_sync(FULL, s, 1);
        if (lane < 16) {
            float rs = rsqrtf(fmaxf(s, 1e-30f));
            float n  = s * rs;
            float tn = tanhf(n);
            g_qT[(size_t)(32 + lane) * NQ + qi] = v * (tn * rs);
            if (lane == 0) g_xn[qi] = tn * tn;
        } else {
            g_qT[(size_t)(48 + (lane - 16)) * NQ + qi] = v * rsqrtf(s);
        }
    } else if (warp == 2) {
        float h = fmaxf(raw[64 + lane], 0.f);
#pragma unroll
        for (int j = 0; j < 3; j++) {
            float p = h * W2[j * 32 + lane];
            p += __shfl_xor_sync(FULL, p, 16);
            p += __shfl_xor_sync(FULL, p, 8);
            p += __shfl_xor_sync(FULL, p, 4);
            p += __shfl_xor_sync(FULL, p, 2);
            p += __shfl_xor_sync(FULL, p, 1);
            if (lane == 0) {
                p += b2[j];
                float sp = (p > 0.f) ? (p + log1pf(expf(-p))) : log1pf(expf(p));
                g_w[j * NQ + qi] = sp;
            }
        }
    }
}

// ---------------------------------------------------------------------------
// Kernel C: pairwise distances. 32q x 128c tile per block, 128 threads.
// Warp w = q rows 8w..8w+7 (q loads BROADCAST); lane l = c cols {2l,2l+1, 64+2l,65+2l}.
// Thread tile 8q x 4c; packed-k f32x2; per-segment accumulator fold.
// smem layout: [kk][r] of float2 = (feat[2kk][r], feat[2kk+1][r]).
// ---------------------------------------------------------------------------
__global__ __launch_bounds__(128, 2) void pairwise_kernel(
    float* __restrict__ out, int NQ, int NC)
{
    __shared__ __align__(16) float qs2[32 * 32 * 2];    // 8 KB
    __shared__ __align__(16) float cs2[32 * 128 * 2];   // 32 KB
    __shared__ float xns[32], yns[128], w0s[32], w1s[32], w2s[32];

    const int tid = threadIdx.x;
    const int q0 = blockIdx.y * 32;
    const int c0 = blockIdx.x * 128;

    // fill q tile: 32q x 64kf = 512 float4 slots
#pragma unroll
    for (int it = 0; it < 4; it++) {
        int idx4 = tid + it * 128;
        int kf = idx4 >> 3, rq = (idx4 & 7) * 4;
        float4 v = *(const float4*)&g_qT[(size_t)kf * NQ + q0 + rq];
        int base = ((kf >> 1) * 32 + rq) * 2 + (kf & 1);
        qs2[base + 0] = v.x; qs2[base + 2] = v.y;
        qs2[base + 4] = v.z; qs2[base + 6] = v.w;
    }
    // fill c tile: 128c x 64kf = 2048 float4 slots
#pragma unroll
    for (int it = 0; it < 16; it++) {
        int idx4 = tid + it * 128;
        int kf = idx4 >> 5, rc = (idx4 & 31) * 4;
        float4 v = *(const float4*)&g_cT[(size_t)kf * NC + c0 + rc];
        int base = ((kf >> 1) * 128 + rc) * 2 + (kf & 1);
        cs2[base + 0] = v.x; cs2[base + 2] = v.y;
        cs2[base + 4] = v.z; cs2[base + 6] = v.w;
    }
    yns[tid] = g_yn[c0 + tid];
    if (tid < 32) {
        xns[tid] = g_xn[q0 + tid];
        w0s[tid] = g_w[0 * NQ + q0 + tid];
        w1s[tid] = g_w[1 * NQ + q0 + tid];
        w2s[tid] = g_w[2 * NQ + q0 + tid];
    }
    __syncthreads();

    const int lane = tid & 31, w4 = (tid >> 5) * 4;
    const ulonglong2* qp = (const ulonglong2*)qs2;   // 16 per kk row
    const ulonglong2* cp = (const ulonglong2*)cs2;   // 64 per kk row

    ull acc2[32];                    // [q-row 0..7][c 0..3]
    float aE[32], aH[32];

#define MMA_STEP(kk)                                                          \
    {                                                                         \
        ulonglong2 cv0 = cp[(kk) * 64 + lane];        /* lane-distinct */     \
        ulonglong2 cv1 = cp[(kk) * 64 + 32 + lane];                           \
        ulonglong2 qa = qp[(kk) * 16 + w4 + 0];       /* broadcast */         \
        ulonglong2 qb = qp[(kk) * 16 + w4 + 1];                               \
        ulonglong2 qc = qp[(kk) * 16 + w4 + 2];                               \
        ulonglong2 qd = qp[(kk) * 16 + w4 + 3];                               \
        ffma2(acc2[ 0], qa.x, cv0.x); ffma2(acc2[ 1], qa.x, cv0.y);           \
        ffma2(acc2[ 2], qa.x, cv1.x); ffma2(acc2[ 3], qa.x, cv1.y);           \
        ffma2(acc2[ 4], qa.y, cv0.x); ffma2(acc2[ 5], qa.y, cv0.y);           \
        ffma2(acc2[ 6], qa.y, cv1.x); ffma2(acc2[ 7], qa.y, cv1.y);           \
        ffma2(acc2[ 8], qb.x, cv0.x); ffma2(acc2[ 9], qb.x, cv0.y);           \
        ffma2(acc2[10], qb.x, cv1.x); ffma2(acc2[11], qb.x, cv1.y);           \
        ffma2(acc2[12], qb.y, cv0.x); ffma2(acc2[13], qb.y, cv0.y);           \
        ffma2(acc2[14], qb.y, cv1.x); ffma2(acc2[15], qb.y, cv1.y);           \
        ffma2(acc2[16], qc.x, cv0.x); ffma2(acc2[17], qc.x, cv0.y);           \
        ffma2(acc2[18], qc.x, cv1.x); ffma2(acc2[19], qc.x, cv1.y);           \
        ffma2(acc2[20], qc.y, cv0.x); ffma2(acc2[21], qc.y, cv0.y);           \
        ffma2(acc2[22], qc.y, cv1.x); ffma2(acc2[23], qc.y, cv1.y);           \
        ffma2(acc2[24], qd.x, cv0.x); ffma2(acc2[25], qd.x, cv0.y);           \
        ffma2(acc2[26], qd.x, cv1.x); ffma2(acc2[27], qd.x, cv1.y);           \
        ffma2(acc2[28], qd.y, cv0.x); ffma2(acc2[29], qd.y, cv0.y);           \
        ffma2(acc2[30], qd.y, cv1.x); ffma2(acc2[31], qd.y, cv1.y);           \
    }

    // E segment: kk 0..15 (k 0..31)
#pragma unroll
    for (int i = 0; i < 32; i++) acc2[i] = 0ull;
#pragma unroll
    for (int kk = 0; kk < 16; kk++) MMA_STEP(kk);
#pragma unroll
    for (int i = 0; i < 32; i++) { aE[i] = fold2(acc2[i]); acc2[i] = 0ull; }

    // H segment: kk 16..23 (k 32..47)
#pragma unroll
    for (int kk = 16; kk < 24; kk++) MMA_STEP(kk);
#pragma unroll
    for (int i = 0; i < 32; i++) { aH[i] = fold2(acc2[i]); acc2[i] = 0ull; }

    // S segment: kk 24..31 (k 48..63)
#pragma unroll
    for (int kk = 24; kk < 32; kk++) MMA_STEP(kk);

#pragma unroll
    for (int i = 0; i < 8; i++) {
        const int ql   = (w4 * 2) + i;         // w*8 + i
        const float xn   = xns[ql];
        const float beta = 1.f - xn;
        const float w0 = w0s[ql], w1 = w1s[ql], w2 = w2s[ql];
        float r4[4];
#pragma unroll
        for (int j = 0; j < 4; j++) {
            const int cl = (j < 2) ? (lane * 2 + j) : (64 + lane * 2 + (j - 2));
            // euclidean on unit sphere
            float de = 2.f - 2.f * aE[i * 4 + j];
            // spherical
            float dsd = fminf(fmaxf(fold2(acc2[i * 4 + j]), -1.f + EPSF), 1.f - EPSF);
            float ac  = facos(dsd);
            float dss = ac * ac;
            // hyperbolic (Poincare, c=1): dh = 2*atanh(t) = log((den+sn)/(den-sn))
            float dot = aH[i * 4 + j];
            float yn  = yns[cl];
            float alpha  = 1.f - 2.f * dot + yn;
            float num_sq = alpha * alpha * xn - 2.f * alpha * beta * dot + beta * beta * yn;
            float den    = fmaxf(1.f - 2.f * dot + xn * yn, 1e-15f);
            float sn = (num_sq > 0.f) ? fsqrt_pos(num_sq) : 0.f;
            sn = fminf(sn, den * (1.f - EPSF));       // t <= 1 - EPS
            float dh  = __logf(__fdividef(den + sn, den - sn));
            float dhs = dh * dh;
            r4[j] = -(w0 * de + w1 * dhs + w2 * dss);
        }
        float* orow = out + (size_t)(q0 + ql) * NC + c0;
        *(float2*)&orow[lane * 2]      = make_float2(r4[0], r4[1]);
        *(float2*)&orow[64 + lane * 2] = make_float2(r4[2], r4[3]);
    }
#undef MMA_STEP
}

// ---------------------------------------------------------------------------
extern "C" void kernel_launch(void* const* d_in, const int* in_sizes, int n_in,
                              void* d_out, int out_size)
{
    const float* xq      = (const float*)d_in[0];
    const float* xc      = (const float*)d_in[1];
    const float* We      = (const float*)d_in[2];
    const float* be      = (const float*)d_in[3];
    const float* Wh      = (const float*)d_in[4];
    const float* bh      = (const float*)d_in[5];
    const float* Ws      = (const float*)d_in[6];
    const float* bs      = (const float*)d_in[7];
    const float* scale_h = (const float*)d_in[8];
    const float* W1      = (const float*)d_in[9];
    const float* b1      = (const float*)d_in[10];
    const float* W2      = (const float*)d_in[11];
    const float* b2      = (const float*)d_in[12];

    const int NQ = in_sizes[0] / D_IN;   // 512
    const int NC = in_sizes[1] / D_IN;   // 65536

    corpus_proj_kernel<<<NC / 64, 128>>>(xc, We, be, Wh, bh, Ws, bs, scale_h, NC);
    query_proj_kernel<<<NQ, 128>>>(xq, We, be, Wh, bh, Ws, bs, scale_h, W1, b1, W2, b2, NQ);
    pairwise_kernel<<<dim3(NC / 128, NQ / 32), 128>>>((float*)d_out, NQ, NC);
}

// round 12
// speedup vs baseline: 1.7794x; 1.7794x over previous
#include <cuda_runtime.h>
#include <math.h>

#define D_IN 768
#define NQ_MAX 512
#define NC_MAX 65536
#define EPSF 1e-7f

typedef unsigned long long ull;

// Scratch: corpus features transposed [feature k][corpus idx], plus per-row extras.
__device__ float g_cT[64 * NC_MAX];     // k-major corpus features (e:0..31, h:32..47, s:48..63)
__device__ float g_yn[NC_MAX];          // ||c_h||^2 = tanh(n)^2
__device__ float g_qT[64 * NQ_MAX];     // k-major query features
__device__ float g_xn[NQ_MAX];          // ||q_h||^2
__device__ float g_w[3 * NQ_MAX];       // softplus weights per query

// packed f32x2 FMA: d = a*b + d (lanewise on 2 packed floats)
__device__ __forceinline__ void ffma2(ull& d, ull a, ull b) {
    asm("fma.rn.f32x2 %0, %1, %2, %0;" : "+l"(d) : "l"(a), "l"(b));
}
__device__ __forceinline__ float fold2(ull v) {
    return __uint_as_float((unsigned)v) + __uint_as_float((unsigned)(v >> 32));
}
// fast sqrt for strictly-positive x (1 MUFU + 1 mul)
__device__ __forceinline__ float fsqrt_pos(float x) { return x * rsqrtf(x); }
// acos via A&S 4.4.46 (7-term), |abs err| ~2e-8. Input must be in [-1,1].
__device__ __forceinline__ float facos(float x) {
    float t = fabsf(x);
    float u = 1.0f - t;                  // >= EPSF after caller's clamp
    float s = u * rsqrtf(u);             // sqrt(1-t)
    float p = fmaf(t, -0.0012624911f, 0.0066700901f);
    p = fmaf(t, p, -0.0170881256f);
    p = fmaf(t, p,  0.0308918810f);
    p = fmaf(t, p, -0.0501743046f);
    p = fmaf(t, p,  0.0889789874f);
    p = fmaf(t, p, -0.2145988016f);
    p = fmaf(t, p,  1.5707963050f);
    float r = s * p;
    return (x < 0.f) ? (3.14159265358979f - r) : r;
}

// ---------------------------------------------------------------------------
// Kernel A: corpus projection. Block = 64 corpus rows, 256 threads.
// thread (kp = tid&31, rg = tid>>5) computes features kp AND kp+32 for rows
// rg*8 .. rg*8+7. Packed-k f32x2 mainloop; x-tile loads broadcast per warp
// and amortized over the 2 features.  (Round-7 structure: known 182 us.)
// ---------------------------------------------------------------------------
#define XSTRIDE 34   // float2 units per row (32 kk + 2 pad); conflict-free

__global__ __launch_bounds__(256, 2) void corpus_proj_kernel(
    const float* __restrict__ xc,
    const float* __restrict__ We, const float* __restrict__ be,
    const float* __restrict__ Wh, const float* __restrict__ bh,
    const float* __restrict__ Ws, const float* __restrict__ bs,
    const float* __restrict__ scale_h_p, int NC)
{
    __shared__ __align__(16) float pool[2 * 64 * XSTRIDE * 2];
    __shared__ float sm_yn[64];
    float2* xs2 = (float2*)pool;                    // [row][kk]
    float2* wt2 = (float2*)pool + 64 * XSTRIDE;     // [feat][kk]

    const int tid = threadIdx.x;
    const int kp  = tid & 31;          // feature A = kp (e), feature B = kp+32 (h/s)
    const int rg  = tid >> 5;          // 0..7, 8 rows each
    const int c0  = blockIdx.x * 64;
    const int fB  = kp + 32;

    const float biasA = be[kp];
    const float biasB = (kp < 16) ? bh[kp] : bs[kp - 16];

    ull accA[8], accB[8];
#pragma unroll
    for (int i = 0; i < 8; i++) { accA[i] = 0ull; accB[i] = 0ull; }

    const int j4 = tid & 15;           // float4 column within tile
    const int r0 = tid >> 4;           // base row / feature for loads

    for (int k0 = 0; k0 < D_IN; k0 += 64) {
        __syncthreads();
        // x tile: 64 rows x 64 k as float4 LDG, STS.128 into [row][kk] pairs
#pragma unroll
        for (int it = 0; it < 4; it++) {
            int r = r0 + it * 16;
            float4 v = *(const float4*)&xc[(size_t)(c0 + r) * D_IN + k0 + j4 * 4];
            *(float4*)&xs2[r * XSTRIDE + j4 * 2] = v;
        }
        // weight tile: wt2[kf][kk] pairs along input dim
#pragma unroll
        for (int it = 0; it < 4; it++) {
            int kf = r0 + it * 16;
            const float* wr = (kf < 32) ? (We + kf * D_IN)
                            : (kf < 48) ? (Wh + (kf - 32) * D_IN)
                                        : (Ws + (kf - 48) * D_IN);
            float4 v = *(const float4*)&wr[k0 + j4 * 4];
            *(float4*)&wt2[kf * XSTRIDE + j4 * 2] = v;
        }
        __syncthreads();

        const float2* xrow = xs2 + rg * 8 * XSTRIDE;   // uniform per warp -> broadcast
#pragma unroll 8
        for (int kk = 0; kk < 32; kk += 2) {
            ulonglong2 wA = *(const ulonglong2*)&wt2[kp * XSTRIDE + kk];
            ulonglong2 wB = *(const ulonglong2*)&wt2[fB * XSTRIDE + kk];
#pragma unroll
            for (int u = 0; u < 8; u++) {
                ulonglong2 xv = *(const ulonglong2*)&xrow[u * XSTRIDE + kk]; // broadcast
                ffma2(accA[u], xv.x, wA.x);
                ffma2(accA[u], xv.y, wA.y);
                ffma2(accB[u], xv.x, wB.x);
                ffma2(accB[u], xv.y, wB.y);
            }
        }
    }

    // fold packed halves, add bias (+ scale_h for hyperbolic branch)
    const float sh = scale_h_p[0];
    const bool isH = (kp < 16);        // feature B type
    float aA[8], aB[8];
#pragma unroll
    for (int i = 0; i < 8; i++) {
        aA[i] = fold2(accA[i]) + biasA;
        float v = fold2(accB[i]) + biasB;
        if (isH) v *= sh;
        aB[i] = v;
    }

    const unsigned FULL = 0xffffffffu;
    // feature A: e-norm over full warp
#pragma unroll
    for (int i = 0; i < 8; i++) {
        float s = aA[i] * aA[i];
        s += __shfl_xor_sync(FULL, s, 16);
        s += __shfl_xor_sync(FULL, s, 8);
        s += __shfl_xor_sync(FULL, s, 4);
        s += __shfl_xor_sync(FULL, s, 2);
        s += __shfl_xor_sync(FULL, s, 1);
        aA[i] *= rsqrtf(s);
    }
    // feature B: lanes 0..15 = h (expmap0), lanes 16..31 = s; 16-lane groups
#pragma unroll
    for (int i = 0; i < 8; i++) {
        float s = aB[i] * aB[i];
        s += __shfl_xor_sync(FULL, s, 8);
        s += __shfl_xor_sync(FULL, s, 4);
        s += __shfl_xor_sync(FULL, s, 2);
        s += __shfl_xor_sync(FULL, s, 1);
        if (isH) {
            float rs = rsqrtf(fmaxf(s, 1e-30f));   // 1/n
            float n  = s * rs;                      // n = sqrt(s)
            float tn = tanhf(n);
            aB[i] = aB[i] * (tn * rs);
            if (kp == 0) sm_yn[rg * 8 + i] = tn * tn;
        } else {
            aB[i] *= rsqrtf(s);
        }
    }

    // transpose through smem (overlay pool) for coalesced k-major global writes
    __syncthreads();
    float* st = pool;   // needs 64*65 = 4160 floats; pool has 8704
#pragma unroll
    for (int i = 0; i < 8; i++) {
        st[kp * 65 + rg * 8 + i] = aA[i];
        st[fB * 65 + rg * 8 + i] = aB[i];
    }
    __syncthreads();
#pragma unroll
    for (int it = 0; it < 16; it++) {
        int idx = tid + it * 256;
        int kf = idx >> 6, r = idx & 63;
        g_cT[(size_t)kf * NC + c0 + r] = st[kf * 65 + r];
    }
    if (tid < 64) g_yn[c0 + tid] = sm_yn[tid];
}

// ---------------------------------------------------------------------------
// Kernel B: query projection + softplus-MLP weights. One block per query.
// ---------------------------------------------------------------------------
__global__ __launch_bounds__(128) void query_proj_kernel(
    const float* __restrict__ xq,
    const float* __restrict__ We, const float* __restrict__ be,
    const float* __restrict__ Wh, const float* __restrict__ bh,
    const float* __restrict__ Ws, const float* __restrict__ bs,
    const float* __restrict__ scale_h_p,
    const float* __restrict__ W1, const float* __restrict__ b1,
    const float* __restrict__ W2, const float* __restrict__ b2,
    int NQ)
{
    __shared__ float x[D_IN];
    __shared__ float raw[96];
    const int tid = threadIdx.x;
    const int qi  = blockIdx.x;

    for (int j = tid; j < D_IN; j += 128) x[j] = xq[(size_t)qi * D_IN + j];
    __syncthreads();

    if (tid < 96) {
        const float* Wr; float b;
        if (tid < 32)      { Wr = We + tid * D_IN;        b = be[tid]; }
        else if (tid < 48) { Wr = Wh + (tid - 32) * D_IN; b = bh[tid - 32]; }
        else if (tid < 64) { Wr = Ws + (tid - 48) * D_IN; b = bs[tid - 48]; }
        else               { Wr = W1 + (tid - 64) * D_IN; b = b1[tid - 64]; }
        float a0 = 0.f, a1 = 0.f, a2 = 0.f, a3 = 0.f;
#pragma unroll 4
        for (int j = 0; j < D_IN; j += 4) {
            const float4 wv = *(const float4*)&Wr[j];
            a0 = fmaf(x[j + 0], wv.x, a0);
            a1 = fmaf(x[j + 1], wv.y, a1);
            a2 = fmaf(x[j + 2], wv.z, a2);
            a3 = fmaf(x[j + 3], wv.w, a3);
        }
        float acc = (a0 + a1) + (a2 + a3) + b;
        if (tid >= 32 && tid < 48) acc *= scale_h_p[0];
        raw[tid] = acc;
    }
    __syncthreads();

    const unsigned FULL = 0xffffffffu;
    const int warp = tid >> 5, lane = tid & 31;
    if (warp == 0) {
        float v = raw[lane];
        float s = v * v;
        s += __shfl_xor_sync(FULL, s, 16);
        s += __shfl_xor_sync(FULL, s, 8);
        s += __shfl_xor_sync(FULL, s, 4);
        s += __shfl_xor_sync(FULL, s, 2);
        s += __shfl_xor_sync(FULL, s, 1);
        g_qT[(size_t)lane * NQ + qi] = v * rsqrtf(s);
    } else if (warp == 1) {
        float v = (lane < 16) ? raw[32 + lane] : raw[48 + (lane - 16)];
        float s = v * v;
        s += __shfl_xor_sync(FULL, s, 8);
        s += __shfl_xor_sync(FULL, s, 4);
        s += __shfl_xor_sync(FULL, s, 2);
        s += __shfl_xor_sync(FULL, s, 1);
        if (lane < 16) {
            float rs = rsqrtf(fmaxf(s, 1e-30f));
            float n  = s * rs;
            float tn = tanhf(n);
            g_qT[(size_t)(32 + lane) * NQ + qi] = v * (tn * rs);
            if (lane == 0) g_xn[qi] = tn * tn;
        } else {
            g_qT[(size_t)(48 + (lane - 16)) * NQ + qi] = v * rsqrtf(s);
        }
    } else if (warp == 2) {
        float h = fmaxf(raw[64 + lane], 0.f);
#pragma unroll
        for (int j = 0; j < 3; j++) {
            float p = h * W2[j * 32 + lane];
            p += __shfl_xor_sync(FULL, p, 16);
            p += __shfl_xor_sync(FULL, p, 8);
            p += __shfl_xor_sync(FULL, p, 4);
            p += __shfl_xor_sync(FULL, p, 2);
            p += __shfl_xor_sync(FULL, p, 1);
            if (lane == 0) {
                p += b2[j];
                float sp = (p > 0.f) ? (p + log1pf(expf(-p))) : log1pf(expf(p));
                g_w[j * NQ + qi] = sp;
            }
        }
    }
}

// ---------------------------------------------------------------------------
// Kernel C: pairwise distances. 64q x 64c tile per block, 256 threads.
// Warp w = q rows 8w..8w+7 (q loads BROADCAST); lane l = c cols 2l,2l+1.
// Thread tile 8q x 2c; packed-k f32x2; per-segment accumulator fold.
// (Round-7 structure + facos/rsqrt epilogue diet.)
// ---------------------------------------------------------------------------
__global__ __launch_bounds__(256, 2) void pairwise_kernel(
    float* __restrict__ out, int NQ, int NC)
{
    __shared__ __align__(16) float qs2[32 * 64 * 2];
    __shared__ __align__(16) float cs2[32 * 64 * 2];
    __shared__ float xns[64], yns[64], w0s[64], w1s[64], w2s[64];

    const int tid = threadIdx.x;
    const int q0 = blockIdx.y * 64;
    const int c0 = blockIdx.x * 64;

#pragma unroll
    for (int it = 0; it < 16; it++) {
        int idx = tid + it * 256;       // 0..4095
        int kf = idx >> 6, r = idx & 63;
        int saddr = ((kf >> 1) * 64 + r) * 2 + (kf & 1);
        qs2[saddr] = g_qT[(size_t)kf * NQ + q0 + r];
        cs2[saddr] = g_cT[(size_t)kf * NC + c0 + r];
    }
    if (tid < 64) {
        xns[tid] = g_xn[q0 + tid];
        yns[tid] = g_yn[c0 + tid];
        w0s[tid] = g_w[0 * NQ + q0 + tid];
        w1s[tid] = g_w[1 * NQ + q0 + tid];
        w2s[tid] = g_w[2 * NQ + q0 + tid];
    }
    __syncthreads();

    const int lane = tid & 31, w = tid >> 5;
    const ulonglong2* qp = (const ulonglong2*)qs2;   // 32 ulonglong2 per kk row
    const ulonglong2* cp = (const ulonglong2*)cs2;

    ull acc2[16];                    // [q-row 0..7][c 0..1]
    float aE[16], aH[16];

#define MMA_STEP(kk)                                                        \
    {                                                                       \
        ulonglong2 cv = cp[(kk) * 32 + lane];            /* lane-distinct */\
        ulonglong2 q0v = qp[(kk) * 32 + w * 4 + 0];      /* broadcast */    \
        ulonglong2 q1v = qp[(kk) * 32 + w * 4 + 1];                         \
        ulonglong2 q2v = qp[(kk) * 32 + w * 4 + 2];                         \
        ulonglong2 q3v = qp[(kk) * 32 + w * 4 + 3];                         \
        ffma2(acc2[ 0], q0v.x, cv.x); ffma2(acc2[ 1], q0v.x, cv.y);         \
        ffma2(acc2[ 2], q0v.y, cv.x); ffma2(acc2[ 3], q0v.y, cv.y);         \
        ffma2(acc2[ 4], q1v.x, cv.x); ffma2(acc2[ 5], q1v.x, cv.y);         \
        ffma2(acc2[ 6], q1v.y, cv.x); ffma2(acc2[ 7], q1v.y, cv.y);         \
        ffma2(acc2[ 8], q2v.x, cv.x); ffma2(acc2[ 9], q2v.x, cv.y);         \
        ffma2(acc2[10], q2v.y, cv.x); ffma2(acc2[11], q2v.y, cv.y);         \
        ffma2(acc2[12], q3v.x, cv.x); ffma2(acc2[13], q3v.x, cv.y);         \
        ffma2(acc2[14], q3v.y, cv.x); ffma2(acc2[15], q3v.y, cv.y);         \
    }

    // E segment: kk 0..15 (k 0..31)
#pragma unroll
    for (int i = 0; i < 16; i++) acc2[i] = 0ull;
#pragma unroll
    for (int kk = 0; kk < 16; kk++) MMA_STEP(kk);
#pragma unroll
    for (int i = 0; i < 16; i++) { aE[i] = fold2(acc2[i]); acc2[i] = 0ull; }

    // H segment: kk 16..23 (k 32..47)
#pragma unroll
    for (int kk = 16; kk < 24; kk++) MMA_STEP(kk);
#pragma unroll
    for (int i = 0; i < 16; i++) { aH[i] = fold2(acc2[i]); acc2[i] = 0ull; }

    // S segment: kk 24..31 (k 48..63)
#pragma unroll
    for (int kk = 24; kk < 32; kk++) MMA_STEP(kk);

#pragma unroll
    for (int i = 0; i < 8; i++) {
        const int ql   = w * 8 + i;
        const float xn   = xns[ql];
        const float beta = 1.f - xn;
        const float w0 = w0s[ql], w1 = w1s[ql], w2 = w2s[ql];
        float r2[2];
#pragma unroll
        for (int j = 0; j < 2; j++) {
            const int cl = lane * 2 + j;
            // euclidean on unit sphere
            float de = 2.f - 2.f * aE[i * 2 + j];
            // spherical
            float dsd = fminf(fmaxf(fold2(acc2[i * 2 + j]), -1.f + EPSF), 1.f - EPSF);
            float ac  = facos(dsd);
            float dss = ac * ac;
            // hyperbolic (Poincare, c=1): dh = 2*atanh(t) = log((den+sn)/(den-sn))
            float dot = aH[i * 2 + j];
            float yn  = yns[cl];
            float alpha  = 1.f - 2.f * dot + yn;
            float num_sq = alpha * alpha * xn - 2.f * alpha * beta * dot + beta * beta * yn;
            float den    = fmaxf(1.f - 2.f * dot + xn * yn, 1e-15f);
            float sn = (num_sq > 0.f) ? fsqrt_pos(num_sq) : 0.f;
            sn = fminf(sn, den * (1.f - EPSF));       // t <= 1 - EPS
            float dh  = __logf(__fdividef(den + sn, den - sn));
            float dhs = dh * dh;
            r2[j] = -(w0 * de + w1 * dhs + w2 * dss);
        }
        *(float2*)&out[(size_t)(q0 + ql) * NC + c0 + lane * 2] =
            make_float2(r2[0], r2[1]);
    }
#undef MMA_STEP
}

// ---------------------------------------------------------------------------
extern "C" void kernel_launch(void* const* d_in, const int* in_sizes, int n_in,
                              void* d_out, int out_size)
{
    const float* xq      = (const float*)d_in[0];
    const float* xc      = (const float*)d_in[1];
    const float* We      = (const float*)d_in[2];
    const float* be      = (const float*)d_in[3];
    const float* Wh      = (const float*)d_in[4];
    const float* bh      = (const float*)d_in[5];
    const float* Ws      = (const float*)d_in[6];
    const float* bs      = (const float*)d_in[7];
    const float* scale_h = (const float*)d_in[8];
    const float* W1      = (const float*)d_in[9];
    const float* b1      = (const float*)d_in[10];
    const float* W2      = (const float*)d_in[11];
    const float* b2      = (const float*)d_in[12];

    const int NQ = in_sizes[0] / D_IN;   // 512
    const int NC = in_sizes[1] / D_IN;   // 65536

    corpus_proj_kernel<<<NC / 64, 256>>>(xc, We, be, Wh, bh, Ws, bs, scale_h, NC);
    query_proj_kernel<<<NQ, 128>>>(xq, We, be, Wh, bh, Ws, bs, scale_h, W1, b1, W2, b2, NQ);
    pairwise_kernel<<<dim3(NC / 64, NQ / 64), 256>>>((float*)d_out, NQ, NC);
}

// round 15
// speedup vs baseline: 1.7910x; 1.0065x over previous
#include <cuda_runtime.h>
#include <math.h>

#define D_IN 768
#define NQ_MAX 512
#define NC_MAX 65536
#define EPSF 1e-7f

typedef unsigned long long ull;

// Scratch: corpus features transposed [feature k][corpus idx], plus per-row extras.
__device__ float g_cT[64 * NC_MAX];     // k-major corpus features (e:0..31, h:32..47, s:48..63)
__device__ float g_yn[NC_MAX];          // ||c_h||^2 = tanh(n)^2
__device__ float g_qT[64 * NQ_MAX];     // k-major query features
__device__ float g_xn[NQ_MAX];          // ||q_h||^2
__device__ float g_w[3 * NQ_MAX];       // softplus weights per query

// packed f32x2 FMA: d = a*b + d (lanewise on 2 packed floats)
__device__ __forceinline__ void ffma2(ull& d, ull a, ull b) {
    asm("fma.rn.f32x2 %0, %1, %2, %0;" : "+l"(d) : "l"(a), "l"(b));
}
__device__ __forceinline__ float fold2(ull v) {
    return __uint_as_float((unsigned)v) + __uint_as_float((unsigned)(v >> 32));
}
// fast sqrt for strictly-positive x (1 MUFU + 1 mul)
__device__ __forceinline__ float fsqrt_pos(float x) { return x * rsqrtf(x); }
// acos via A&S 4.4.46 (7-term), |abs err| ~2e-8. Input must be in [-1,1].
__device__ __forceinline__ float facos(float x) {
    float t = fabsf(x);
    float u = 1.0f - t;
    float s = u * rsqrtf(u);
    float p = fmaf(t, -0.0012624911f, 0.0066700901f);
    p = fmaf(t, p, -0.0170881256f);
    p = fmaf(t, p,  0.0308918810f);
    p = fmaf(t, p, -0.0501743046f);
    p = fmaf(t, p,  0.0889789874f);
    p = fmaf(t, p, -0.2145988016f);
    p = fmaf(t, p,  1.5707963050f);
    float r = s * p;
    return (x < 0.f) ? (3.14159265358979f - r) : r;
}

// ---------------------------------------------------------------------------
// Kernel A: corpus projection. Block = 128 corpus rows, 256 threads.
// thread (kp = tid&15, rg = tid>>4) computes 4 features kp, kp+16, kp+32,
// kp+48 for rows rg*8 .. rg*8+7. Packed-k f32x2; x-tile loads are 2-address
// per warp (near-broadcast), w loads half-warp duplicated -> 0.25 wf/FFMA2.
// Dynamic smem: x tile 128x34 float2 + w tile 64x34 float2 = 52224 B.
// ---------------------------------------------------------------------------
#define XSTRIDE 34   // float2 units per row (32 kk + 2 pad)
#define CORPUS_DSMEM (128 * XSTRIDE * 8 + 64 * XSTRIDE * 8)   // 52224 B

__global__ __launch_bounds__(256, 2) void corpus_proj_kernel(
    const float* __restrict__ xc,
    const float* __restrict__ We, const float* __restrict__ be,
    const float* __restrict__ Wh, const float* __restrict__ bh,
    const float* __restrict__ Ws, const float* __restrict__ bs,
    const float* __restrict__ scale_h_p, int NC)
{
    extern __shared__ __align__(16) char dsm[];
    float2* xs2 = (float2*)dsm;                       // [row 0..127][kk]
    float2* wt2 = (float2*)dsm + 128 * XSTRIDE;       // [feat 0..63][kk]
    float*  st  = (float*)dsm;                        // transpose overlay (64*130 floats)
    __shared__ float sm_yn[128];

    const int tid = threadIdx.x;
    const int kp  = tid & 15;          // feature base
    const int rg  = tid >> 4;          // 0..15, rows rg*8..rg*8+7
    const int c0  = blockIdx.x * 128;
    const int f0 = kp, f1 = kp + 16, f2 = kp + 32, f3 = kp + 48;

    const float b0 = be[f0];
    const float b1 = be[f1];
    const float b2 = bh[kp];
    const float b3 = bs[kp];
    const float sh = scale_h_p[0];

    ull a0[8], a1[8], a2[8], a3[8];
#pragma unroll
    for (int i = 0; i < 8; i++) { a0[i] = 0ull; a1[i] = 0ull; a2[i] = 0ull; a3[i] = 0ull; }

    const int j4 = tid & 15;           // float4 column within tile
    const int r0 = tid >> 4;           // 0..15

#pragma unroll 1
    for (int k0 = 0; k0 < D_IN; k0 += 64) {
        __syncthreads();
        // x tile: 128 rows x 64 k as float4 LDG -> [row][kk] pairs
#pragma unroll
        for (int it = 0; it < 8; it++) {
            int r = r0 + it * 16;
            float4 v = *(const float4*)&xc[(size_t)(c0 + r) * D_IN + k0 + j4 * 4];
            *(float4*)&xs2[r * XSTRIDE + j4 * 2] = v;
        }
        // weight tile: wt2[kf][kk]
#pragma unroll
        for (int it = 0; it < 4; it++) {
            int kf = r0 + it * 16;
            const float* wr = (kf < 32) ? (We + kf * D_IN)
                            : (kf < 48) ? (Wh + (kf - 32) * D_IN)
                                        : (Ws + (kf - 48) * D_IN);
            float4 v = *(const float4*)&wr[k0 + j4 * 4];
            *(float4*)&wt2[kf * XSTRIDE + j4 * 2] = v;
        }
        __syncthreads();

        const float2* xrow = xs2 + rg * 8 * XSTRIDE;   // 2 addrs per warp (half-warp bcast)
#pragma unroll 4
        for (int kk = 0; kk < 32; kk += 2) {
            ulonglong2 w0 = *(const ulonglong2*)&wt2[f0 * XSTRIDE + kk];
            ulonglong2 w1 = *(const ulonglong2*)&wt2[f1 * XSTRIDE + kk];
            ulonglong2 w2 = *(const ulonglong2*)&wt2[f2 * XSTRIDE + kk];
            ulonglong2 w3 = *(const ulonglong2*)&wt2[f3 * XSTRIDE + kk];
#pragma unroll
            for (int u = 0; u < 8; u++) {
                ulonglong2 xv = *(const ulonglong2*)&xrow[u * XSTRIDE + kk];
                ffma2(a0[u], xv.x, w0.x);
                ffma2(a0[u], xv.y, w0.y);
                ffma2(a1[u], xv.x, w1.x);
                ffma2(a1[u], xv.y, w1.y);
                ffma2(a2[u], xv.x, w2.x);
                ffma2(a2[u], xv.y, w2.y);
                ffma2(a3[u], xv.x, w3.x);
                ffma2(a3[u], xv.y, w3.y);
            }
        }
    }

    // fold packed halves, add bias (scale_h on hyperbolic branch)
    float vA[8], vB[8], vC[8], vD[8];
#pragma unroll
    for (int i = 0; i < 8; i++) {
        vA[i] = fold2(a0[i]) + b0;
        vB[i] = fold2(a1[i]) + b1;
        vC[i] = (fold2(a2[i]) + b2) * sh;
        vD[i] = fold2(a3[i]) + b3;
    }

    // 16-lane reductions (feature groups live in 16-lane halves)
    const unsigned FULL = 0xffffffffu;
#pragma unroll
    for (int i = 0; i < 8; i++) {
        // e-norm: feats 0..31 = {kp, kp+16} across 16 lanes
        float se = fmaf(vA[i], vA[i], vB[i] * vB[i]);
        se += __shfl_xor_sync(FULL, se, 8);
        se += __shfl_xor_sync(FULL, se, 4);
        se += __shfl_xor_sync(FULL, se, 2);
        se += __shfl_xor_sync(FULL, se, 1);
        float rse = rsqrtf(se);
        vA[i] *= rse;
        vB[i] *= rse;
        // h: expmap0 over feats 32..47
        float sH = vC[i] * vC[i];
        sH += __shfl_xor_sync(FULL, sH, 8);
        sH += __shfl_xor_sync(FULL, sH, 4);
        sH += __shfl_xor_sync(FULL, sH, 2);
        sH += __shfl_xor_sync(FULL, sH, 1);
        float rsh = rsqrtf(fmaxf(sH, 1e-30f));
        float n   = sH * rsh;
        float tn  = tanhf(n);
        vC[i] *= tn * rsh;
        if (kp == 0) sm_yn[rg * 8 + i] = tn * tn;
        // s-norm over feats 48..63
        float sS = vD[i] * vD[i];
        sS += __shfl_xor_sync(FULL, sS, 8);
        sS += __shfl_xor_sync(FULL, sS, 4);
        sS += __shfl_xor_sync(FULL, sS, 2);
        sS += __shfl_xor_sync(FULL, sS, 1);
        vD[i] *= rsqrtf(sS);
    }

    // transpose through smem (overlay pool) for coalesced k-major writes
    __syncthreads();
#pragma unroll
    for (int i = 0; i < 8; i++) {
        int row = rg * 8 + i;
        st[f0 * 130 + row] = vA[i];
        st[f1 * 130 + row] = vB[i];
        st[f2 * 130 + row] = vC[i];
        st[f3 * 130 + row] = vD[i];
    }
    __syncthreads();
#pragma unroll
    for (int it = 0; it < 32; it++) {
        int idx = tid + it * 256;      // 0..8191
        int kf = idx >> 7, r = idx & 127;
        g_cT[(size_t)kf * NC + c0 + r] = st[kf * 130 + r];
    }
    if (tid < 128) g_yn[c0 + tid] = sm_yn[tid];
}

// ---------------------------------------------------------------------------
// Kernel B: query projection + softplus-MLP weights. One block per query.
// ---------------------------------------------------------------------------
__global__ __launch_bounds__(128) void query_proj_kernel(
    const float* __restrict__ xq,
    const float* __restrict__ We, const float* __restrict__ be,
    const float* __restrict__ Wh, const float* __restrict__ bh,
    const float* __restrict__ Ws, const float* __restrict__ bs,
    const float* __restrict__ scale_h_p,
    const float* __restrict__ W1, const float* __restrict__ b1,
    const float* __restrict__ W2, const float* __restrict__ b2,
    int NQ)
{
    __shared__ float x[D_IN];
    __shared__ float raw[96];
    const int tid = threadIdx.x;
    const int qi  = blockIdx.x;

    for (int j = tid; j < D_IN; j += 128) x[j] = xq[(size_t)qi * D_IN + j];
    __syncthreads();

    if (tid < 96) {
        const float* Wr; float b;
        if (tid < 32)      { Wr = We + tid * D_IN;        b = be[tid]; }
        else if (tid < 48) { Wr = Wh + (tid - 32) * D_IN; b = bh[tid - 32]; }
        else if (tid < 64) { Wr = Ws + (tid - 48) * D_IN; b = bs[tid - 48]; }
        else               { Wr = W1 + (tid - 64) * D_IN; b = b1[tid - 64]; }
        float a0 = 0.f, a1 = 0.f, a2 = 0.f, a3 = 0.f;
#pragma unroll 4
        for (int j = 0; j < D_IN; j += 4) {
            const float4 wv = *(const float4*)&Wr[j];
            a0 = fmaf(x[j + 0], wv.x, a0);
            a1 = fmaf(x[j + 1], wv.y, a1);
            a2 = fmaf(x[j + 2], wv.z, a2);
            a3 = fmaf(x[j + 3], wv.w, a3);
        }
        float acc = (a0 + a1) + (a2 + a3) + b;
        if (tid >= 32 && tid < 48) acc *= scale_h_p[0];
        raw[tid] = acc;
    }
    __syncthreads();

    const unsigned FULL = 0xffffffffu;
    const int warp = tid >> 5, lane = tid & 31;
    if (warp == 0) {
        float v = raw[lane];
        float s = v * v;
        s += __shfl_xor_sync(FULL, s, 16);
        s += __shfl_xor_sync(FULL, s, 8);
        s += __shfl_xor_sync(FULL, s, 4);
        s += __shfl_xor_sync(FULL, s, 2);
        s += __shfl_xor_sync(FULL, s, 1);
        g_qT[(size_t)lane * NQ + qi] = v * rsqrtf(s);
    } else if (warp == 1) {
        float v = (lane < 16) ? raw[32 + lane] : raw[48 + (lane - 16)];
        float s = v * v;
        s += __shfl_xor_sync(FULL, s, 8);
        s += __shfl_xor_sync(FULL, s, 4);
        s += __shfl_xor_sync(FULL, s, 2);
        s += __shfl_xor_sync(FULL, s, 1);
        if (lane < 16) {
            float rs = rsqrtf(fmaxf(s, 1e-30f));
            float n  = s * rs;
            float tn = tanhf(n);
            g_qT[(size_t)(32 + lane) * NQ + qi] = v * (tn * rs);
            if (lane == 0) g_xn[qi] = tn * tn;
        } else {
            g_qT[(size_t)(48 + (lane - 16)) * NQ + qi] = v * rsqrtf(s);
        }
    } else if (warp == 2) {
        float h = fmaxf(raw[64 + lane], 0.f);
#pragma unroll
        for (int j = 0; j < 3; j++) {
            float p = h * W2[j * 32 + lane];
            p += __shfl_xor_sync(FULL, p, 16);
            p += __shfl_xor_sync(FULL, p, 8);
            p += __shfl_xor_sync(FULL, p, 4);
            p += __shfl_xor_sync(FULL, p, 2);
            p += __shfl_xor_sync(FULL, p, 1);
            if (lane == 0) {
                p += b2[j];
                float sp = (p > 0.f) ? (p + log1pf(expf(-p))) : log1pf(expf(p));
                g_w[j * NQ + qi] = sp;
            }
        }
    }
}

// ---------------------------------------------------------------------------
// Kernel C: pairwise distances. 64q x 64c tile per block, 256 threads.
// Warp w = q rows 8w..8w+7 (q loads BROADCAST); lane l = c cols 2l,2l+1.
// Thread tile 8q x 2c; packed-k f32x2; per-segment accumulator fold.
// (408-us baseline structure, unchanged.)
// ---------------------------------------------------------------------------
__global__ __launch_bounds__(256, 2) void pairwise_kernel(
    float* __restrict__ out, int NQ, int NC)
{
    __shared__ __align__(16) float qs2[32 * 64 * 2];
    __shared__ __align__(16) float cs2[32 * 64 * 2];
    __shared__ float xns[64], yns[64], w0s[64], w1s[64], w2s[64];

    const int tid = threadIdx.x;
    const int q0 = blockIdx.y * 64;
    const int c0 = blockIdx.x * 64;

#pragma unroll
    for (int it = 0; it < 16; it++) {
        int idx = tid + it * 256;
        int kf = idx >> 6, r = idx & 63;
        int saddr = ((kf >> 1) * 64 + r) * 2 + (kf & 1);
        qs2[saddr] = g_qT[(size_t)kf * NQ + q0 + r];
        cs2[saddr] = g_cT[(size_t)kf * NC + c0 + r];
    }
    if (tid < 64) {
        xns[tid] = g_xn[q0 + tid];
        yns[tid] = g_yn[c0 + tid];
        w0s[tid] = g_w[0 * NQ + q0 + tid];
        w1s[tid] = g_w[1 * NQ + q0 + tid];
        w2s[tid] = g_w[2 * NQ + q0 + tid];
    }
    __syncthreads();

    const int lane = tid & 31, w = tid >> 5;
    const ulonglong2* qp = (const ulonglong2*)qs2;
    const ulonglong2* cp = (const ulonglong2*)cs2;

    ull acc2[16];
    float aE[16], aH[16];

#define MMA_STEP(kk)                                                        \
    {                                                                       \
        ulonglong2 cv = cp[(kk) * 32 + lane];                               \
        ulonglong2 q0v = qp[(kk) * 32 + w * 4 + 0];                         \
        ulonglong2 q1v = qp[(kk) * 32 + w * 4 + 1];                         \
        ulonglong2 q2v = qp[(kk) * 32 + w * 4 + 2];                         \
        ulonglong2 q3v = qp[(kk) * 32 + w * 4 + 3];                         \
        ffma2(acc2[ 0], q0v.x, cv.x); ffma2(acc2[ 1], q0v.x, cv.y);         \
        ffma2(acc2[ 2], q0v.y, cv.x); ffma2(acc2[ 3], q0v.y, cv.y);         \
        ffma2(acc2[ 4], q1v.x, cv.x); ffma2(acc2[ 5], q1v.x, cv.y);         \
        ffma2(acc2[ 6], q1v.y, cv.x); ffma2(acc2[ 7], q1v.y, cv.y);         \
        ffma2(acc2[ 8], q2v.x, cv.x); ffma2(acc2[ 9], q2v.x, cv.y);         \
        ffma2(acc2[10], q2v.y, cv.x); ffma2(acc2[11], q2v.y, cv.y);         \
        ffma2(acc2[12], q3v.x, cv.x); ffma2(acc2[13], q3v.x, cv.y);         \
        ffma2(acc2[14], q3v.y, cv.x); ffma2(acc2[15], q3v.y, cv.y);         \
    }

#pragma unroll
    for (int i = 0; i < 16; i++) acc2[i] = 0ull;
#pragma unroll
    for (int kk = 0; kk < 16; kk++) MMA_STEP(kk);
#pragma unroll
    for (int i = 0; i < 16; i++) { aE[i] = fold2(acc2[i]); acc2[i] = 0ull; }

#pragma unroll
    for (int kk = 16; kk < 24; kk++) MMA_STEP(kk);
#pragma unroll
    for (int i = 0; i < 16; i++) { aH[i] = fold2(acc2[i]); acc2[i] = 0ull; }

#pragma unroll
    for (int kk = 24; kk < 32; kk++) MMA_STEP(kk);

#pragma unroll
    for (int i = 0; i < 8; i++) {
        const int ql   = w * 8 + i;
        const float xn   = xns[ql];
        const float beta = 1.f - xn;
        const float w0 = w0s[ql], w1 = w1s[ql], w2 = w2s[ql];
        float r2[2];
#pragma unroll
        for (int j = 0; j < 2; j++) {
            const int cl = lane * 2 + j;
            float de = 2.f - 2.f * aE[i * 2 + j];
            float dsd = fminf(fmaxf(fold2(acc2[i * 2 + j]), -1.f + EPSF), 1.f - EPSF);
            float ac  = facos(dsd);
            float dss = ac * ac;
            float dot = aH[i * 2 + j];
            float yn  = yns[cl];
            float alpha  = 1.f - 2.f * dot + yn;
            float num_sq = alpha * alpha * xn - 2.f * alpha * beta * dot + beta * beta * yn;
            float den    = fmaxf(1.f - 2.f * dot + xn * yn, 1e-15f);
            float sn = (num_sq > 0.f) ? fsqrt_pos(num_sq) : 0.f;
            sn = fminf(sn, den * (1.f - EPSF));
            float dh  = __logf(__fdividef(den + sn, den - sn));
            float dhs = dh * dh;
            r2[j] = -(w0 * de + w1 * dhs + w2 * dss);
        }
        *(float2*)&out[(size_t)(q0 + ql) * NC + c0 + lane * 2] =
            make_float2(r2[0], r2[1]);
    }
#undef MMA_STEP
}

// ---------------------------------------------------------------------------
extern "C" void kernel_launch(void* const* d_in, const int* in_sizes, int n_in,
                              void* d_out, int out_size)
{
    const float* xq      = (const float*)d_in[0];
    const float* xc      = (const float*)d_in[1];
    const float* We      = (const float*)d_in[2];
    const float* be      = (const float*)d_in[3];
    const float* Wh      = (const float*)d_in[4];
    const float* bh      = (const float*)d_in[5];
    const float* Ws      = (const float*)d_in[6];
    const float* bs      = (const float*)d_in[7];
    const float* scale_h = (const float*)d_in[8];
    const float* W1      = (const float*)d_in[9];
    const float* b1      = (const float*)d_in[10];
    const float* W2      = (const float*)d_in[11];
    const float* b2      = (const float*)d_in[12];

    const int NQ = in_sizes[0] / D_IN;   // 512
    const int NC = in_sizes[1] / D_IN;   // 65536

    cudaFuncSetAttribute(corpus_proj_kernel,
                         cudaFuncAttributeMaxDynamicSharedMemorySize, CORPUS_DSMEM);

    corpus_proj_kernel<<<NC / 128, 256, CORPUS_DSMEM>>>(xc, We, be, Wh, bh, Ws, bs, scale_h, NC);
    query_proj_kernel<<<NQ, 128>>>(xq, We, be, Wh, bh, Ws, bs, scale_h, W1, b1, W2, b2, NQ);
    pairwise_kernel<<<dim3(NC / 64, NQ / 64), 256>>>((float*)d_out, NQ, NC);
}